// round 1
// baseline (speedup 1.0000x reference)
#include <cuda_runtime.h>
#include <math.h>

// ---------------------------------------------------------------------------
// LLIE loss: 2x SSIM(7x7, valid) + L1/MSE reductions + 256-bin histogram color
// loss + BCE-with-logits GAN loss.
//
// Shapes: B=16, C=3, H=W=512. SSIM valid output 506x506.
// Inputs (metadata order):
//   0 img        (16,3,512,512) f32
//   1 target     (16,3,512,512) f32
//   2 comp0      (16,3,512,512) f32
//   3 comp1      (16,1,512,512) f32
//   4 comp2      (16,1,512,512) f32
//   5 real_comp0 (16,3,512,512) f32
//   6 real_comp1 (16,1,512,512) f32
//   7 color_hist (16,3,256)     f32
//   8 score      (16,1)         f32
// Output: [loss, breakdown(6)] -> 7 f32 (handles out_size==6 too).
// ---------------------------------------------------------------------------

#define IMG_W   512
#define IMG_HW  (512 * 512)
#define OUT_W   506
#define NBC     48            // B*C
#define N3      12582912.0    // B*3*H*W
#define NHW     4194304.0     // B*H*W

// accumulators: 0 ssim0, 1 ssim1, 2 l1(c0,r0), 3 l1(img,c0*c1), 4 l1(tgt,r0*r1),
//               5 mse light, 6 mse out, 7 color, 8 gan
__device__ double g_acc[9];
__device__ unsigned int g_hist[NBC * 256];

// ---------------------------------------------------------------------------
__device__ __forceinline__ float blockReduceSum(float v, float* red) {
    #pragma unroll
    for (int o = 16; o > 0; o >>= 1) v += __shfl_down_sync(0xffffffffu, v, o);
    int lane = threadIdx.x & 31, wid = threadIdx.x >> 5;
    if (lane == 0) red[wid] = v;
    __syncthreads();
    v = (threadIdx.x < (blockDim.x >> 5)) ? red[threadIdx.x] : 0.f;
    if (wid == 0) {
        #pragma unroll
        for (int o = 16; o > 0; o >>= 1) v += __shfl_down_sync(0xffffffffu, v, o);
    }
    __syncthreads();   // allow red reuse by a subsequent call
    return v;          // valid on thread 0
}

// ---------------------------------------------------------------------------
__global__ void init_kernel() {
    int i = blockIdx.x * blockDim.x + threadIdx.x;
    if (i < 9) g_acc[i] = 0.0;
    for (int j = i; j < NBC * 256; j += gridDim.x * blockDim.x) g_hist[j] = 0u;
}

// ---------------------------------------------------------------------------
// SSIM over one (b,c) image pair; 32x32 output tile per block.
// Separable 7x7 box filter: horizontal pass into SMEM, vertical pass + formula.
__global__ __launch_bounds__(256) void ssim_kernel(
    const float* __restrict__ x, const float* __restrict__ y, int which)
{
    __shared__ float sx[38][40];
    __shared__ float sy[38][40];
    __shared__ float h0[38][32], h1[38][32], h2[38][32], h3[38][32], h4[38][32];
    __shared__ float red[32];

    const int tid = threadIdx.x;
    const long base = (long)blockIdx.z * IMG_HW;
    const int r0 = blockIdx.y * 32, c0 = blockIdx.x * 32;

    // load 38x38 input region (zero-pad out of range; never used for valid outs)
    for (int i = tid; i < 38 * 38; i += 256) {
        int r = i / 38, c = i % 38;
        int gr = r0 + r, gc = c0 + c;
        float xv = 0.f, yv = 0.f;
        if (gr < IMG_W && gc < IMG_W) {
            long idx = base + (long)gr * IMG_W + gc;
            xv = x[idx];
            yv = y[idx];
        }
        sx[r][c] = xv;
        sy[r][c] = yv;
    }
    __syncthreads();

    // horizontal 7-tap sums of {x, y, xx, yy, xy}
    for (int i = tid; i < 38 * 32; i += 256) {
        int r = i / 32, c = i % 32;
        float ax = 0.f, ay = 0.f, axx = 0.f, ayy = 0.f, axy = 0.f;
        #pragma unroll
        for (int k = 0; k < 7; k++) {
            float xv = sx[r][c + k], yv = sy[r][c + k];
            ax += xv; ay += yv;
            axx += xv * xv; ayy += yv * yv; axy += xv * yv;
        }
        h0[r][c] = ax; h1[r][c] = ay; h2[r][c] = axx; h3[r][c] = ayy; h4[r][c] = axy;
    }
    __syncthreads();

    // vertical 7-tap + SSIM
    float local = 0.f;
    for (int i = tid; i < 32 * 32; i += 256) {
        int r = i >> 5, c = i & 31;
        if (r0 + r < OUT_W && c0 + c < OUT_W) {
            float s1 = 0.f, s2 = 0.f, s3 = 0.f, s4 = 0.f, s5 = 0.f;
            #pragma unroll
            for (int k = 0; k < 7; k++) {
                s1 += h0[r + k][c];
                s2 += h1[r + k][c];
                s3 += h2[r + k][c];
                s4 += h3[r + k][c];
                s5 += h4[r + k][c];
            }
            const float inv = 1.f / 49.f;
            float ux = s1 * inv, uy = s2 * inv;
            float uxx = s3 * inv, uyy = s4 * inv, uxy = s5 * inv;
            const float COVN = 49.f / 48.f;
            float vx  = COVN * (uxx - ux * ux);
            float vy  = COVN * (uyy - uy * uy);
            float vxy = COVN * (uxy - ux * uy);
            const float c1 = 1e-4f, c2 = 9e-4f;
            float A  = (2.f * ux * uy + c1) * (2.f * vxy + c2);
            float Bd = (ux * ux + uy * uy + c1) * (vx + vy + c2);
            local += A / Bd;
        }
    }

    float tot = blockReduceSum(local, red);
    if (tid == 0) atomicAdd(&g_acc[which], (double)tot);
}

// ---------------------------------------------------------------------------
// Fused elementwise pass: L1/MSE reductions + target histogram.
// grid.x = B * 256; each block handles 1024 contiguous pixels of one image.
__global__ __launch_bounds__(256) void elem_kernel(
    const float* __restrict__ img,  const float* __restrict__ target,
    const float* __restrict__ comp0, const float* __restrict__ comp1,
    const float* __restrict__ comp2, const float* __restrict__ real0,
    const float* __restrict__ real1)
{
    __shared__ unsigned int shist[3 * 256];
    __shared__ float red[32];

    const int tid = threadIdx.x;
    for (int i = tid; i < 3 * 256; i += 256) shist[i] = 0u;
    __syncthreads();

    const int b = blockIdx.x >> 8;
    const int chunk = blockIdx.x & 255;
    const int pstart = chunk * 1024;
    const long bHW = (long)b * IMG_HW;
    const long b3HW = (long)b * 3 * IMG_HW;

    float s_cr = 0.f, s_ic = 0.f, s_tr = 0.f, s_light = 0.f, s_mse = 0.f;

    #pragma unroll
    for (int it = 0; it < 4; it++) {
        int pix = pstart + it * 256 + tid;
        float c1v = comp1[bHW + pix];
        float r1v = real1[bHW + pix];
        float c2v = comp2[bHW + pix];
        float dl = c2v - r1v;
        s_light += dl * dl;
        #pragma unroll
        for (int c = 0; c < 3; c++) {
            long idx = b3HW + (long)c * IMG_HW + pix;
            float iv  = img[idx];
            float tv  = target[idx];
            float c0v = comp0[idx];
            float r0v = real0[idx];
            s_cr += fabsf(c0v - r0v);
            s_ic += fabsf(iv - c0v * c1v);
            s_tr += fabsf(tv - r0v * r1v);
            float d = iv - tv;
            s_mse += d * d;
            int bin = (int)rintf(tv * 255.f);
            bin = min(max(bin, 0), 255);
            atomicAdd(&shist[c * 256 + bin], 1u);
        }
    }

    float t;
    t = blockReduceSum(s_cr, red);    if (tid == 0) atomicAdd(&g_acc[2], (double)t);
    t = blockReduceSum(s_ic, red);    if (tid == 0) atomicAdd(&g_acc[3], (double)t);
    t = blockReduceSum(s_tr, red);    if (tid == 0) atomicAdd(&g_acc[4], (double)t);
    t = blockReduceSum(s_light, red); if (tid == 0) atomicAdd(&g_acc[5], (double)t);
    t = blockReduceSum(s_mse, red);   if (tid == 0) atomicAdd(&g_acc[6], (double)t);

    __syncthreads();
    for (int i = tid; i < 3 * 256; i += 256)
        atomicAdd(&g_hist[b * 768 + i], shist[i]);
}

// ---------------------------------------------------------------------------
// Color L1 (vs normalized histogram) + GAN BCE-with-logits. Single block.
__global__ __launch_bounds__(256) void color_gan_kernel(
    const float* __restrict__ color_hist, const float* __restrict__ score)
{
    __shared__ float red[32];
    const float invHW = 1.f / (float)IMG_HW;

    float cs = 0.f;
    for (int i = threadIdx.x; i < NBC * 256; i += 256)
        cs += fabsf(color_hist[i] - (float)g_hist[i] * invHW);

    float gs = 0.f;
    if (threadIdx.x < 16) {
        float z = -score[threadIdx.x];                      // softplus(-s)
        gs = fmaxf(z, 0.f) + log1pf(expf(-fabsf(z)));
    }

    float t;
    t = blockReduceSum(cs, red); if (threadIdx.x == 0) g_acc[7] = (double)t;
    t = blockReduceSum(gs, red); if (threadIdx.x == 0) g_acc[8] = (double)t;
}

// ---------------------------------------------------------------------------
__global__ void finalize_kernel(float* out, int out_size) {
    if (threadIdx.x != 0 || blockIdx.x != 0) return;
    const double nS = 48.0 * 506.0 * 506.0;
    double ssim0 = g_acc[0] / nS;
    double ssim1 = g_acc[1] / nS;
    double r     = (1.0 - ssim0) + g_acc[2] / N3 + g_acc[3] / N3 + g_acc[4] / N3;
    double light = g_acc[5] / NHW;
    double color = g_acc[7] / (48.0 * 256.0);
    double outl  = (1.0 - ssim1) + g_acc[6] / N3;
    double gan   = g_acc[8] / 16.0;
    double loss  = r + light + 0.1 * color + outl + 0.05 * gan;

    float v[7] = {(float)loss, (float)loss, (float)r, (float)light,
                  (float)color, (float)outl, (float)gan};
    const float* src = (out_size == 6) ? (v + 1) : v;
    int n = out_size < 7 ? out_size : 7;
    for (int i = 0; i < n; i++) out[i] = src[i];
}

// ---------------------------------------------------------------------------
extern "C" void kernel_launch(void* const* d_in, const int* in_sizes, int n_in,
                              void* d_out, int out_size) {
    const float* img    = (const float*)d_in[0];
    const float* target = (const float*)d_in[1];
    const float* comp0  = (const float*)d_in[2];
    const float* comp1  = (const float*)d_in[3];
    const float* comp2  = (const float*)d_in[4];
    const float* real0  = (const float*)d_in[5];
    const float* real1  = (const float*)d_in[6];
    const float* chist  = (const float*)d_in[7];
    const float* score  = (const float*)d_in[8];
    float* out = (float*)d_out;

    init_kernel<<<48, 256>>>();

    dim3 sgrid(16, 16, NBC);
    ssim_kernel<<<sgrid, 256>>>(comp0, real0, 0);
    ssim_kernel<<<sgrid, 256>>>(img, target, 1);

    elem_kernel<<<16 * 256, 256>>>(img, target, comp0, comp1, comp2, real0, real1);

    color_gan_kernel<<<1, 256>>>(chist, score);

    finalize_kernel<<<1, 32>>>(out, out_size);
}

// round 2
// speedup vs baseline: 1.3321x; 1.3321x over previous
#include <cuda_runtime.h>
#include <math.h>

// ---------------------------------------------------------------------------
// LLIE loss: 2x SSIM(7x7, valid) + L1/MSE reductions + 256-bin histogram color
// loss + BCE-with-logits GAN loss.  B=16, C=3, H=W=512. SSIM valid out 506x506.
// ---------------------------------------------------------------------------

#define IMG_W   512
#define IMG_HW  (512 * 512)
#define OUT_W   506
#define NBC     48
#define N3      12582912.0
#define NHW     4194304.0

// 0 ssim0, 1 ssim1, 2 l1(c0,r0), 3 l1(img,c0*c1), 4 l1(tgt,r0*r1),
// 5 mse light, 6 mse out, 7 color, 8 gan
__device__ double g_acc[9];
__device__ unsigned int g_hist[NBC * 256];

// ---------------------------------------------------------------------------
__device__ __forceinline__ float blockReduceSum(float v, float* red) {
    #pragma unroll
    for (int o = 16; o > 0; o >>= 1) v += __shfl_down_sync(0xffffffffu, v, o);
    int lane = threadIdx.x & 31, wid = threadIdx.x >> 5;
    if (lane == 0) red[wid] = v;
    __syncthreads();
    v = (threadIdx.x < (blockDim.x >> 5)) ? red[threadIdx.x] : 0.f;
    if (wid == 0) {
        #pragma unroll
        for (int o = 16; o > 0; o >>= 1) v += __shfl_down_sync(0xffffffffu, v, o);
    }
    __syncthreads();
    return v;
}

// ---------------------------------------------------------------------------
__global__ void init_kernel() {
    int i = blockIdx.x * blockDim.x + threadIdx.x;
    if (i < 9) g_acc[i] = 0.0;
    for (int j = i; j < NBC * 256; j += gridDim.x * blockDim.x) g_hist[j] = 0u;
}

// ---------------------------------------------------------------------------
// Sliding-window SSIM. Each thread owns one output column; vertical 7-row box
// sums kept as running sums in registers with a 7-deep register ring (row loop
// unrolled by 7 so ring indices are static). Horizontal 7-tap stats come from
// one shared input row (double-buffered, 1 barrier/row); next row's globals
// are prefetched into registers before the barrier.
// Grid: (2 col-blocks of 256 cols, 8 row strips of 64, 48 planes).
__global__ __launch_bounds__(256) void ssim_kernel(
    const float* __restrict__ x, const float* __restrict__ y, int which)
{
    __shared__ float sx[2][264];
    __shared__ float sy[2][264];
    __shared__ float red[32];

    const int tid = threadIdx.x;
    const int c0 = blockIdx.x << 8;            // 0 or 256
    const int R0 = blockIdx.y * 64;            // output-row strip start
    const int rows = min(64, OUT_W - R0);      // 64 or 58
    const int total = rows + 6;                // input rows this strip
    const long base = (long)blockIdx.z * IMG_HW;
    const int gc = c0 + tid;                   // input col owned / output col
    const bool extra = (tid < 6) && (c0 == 0); // halo cols 256..261 (block 0)
    const bool colok = (gc < OUT_W);

    // block 1: halo slots never written by loads; zero once (no racer there)
    if (c0 != 0 && tid < 8) {
        sx[0][256 + tid] = 0.f; sx[1][256 + tid] = 0.f;
        sy[0][256 + tid] = 0.f; sy[1][256 + tid] = 0.f;
    }

    const float* xr = x + base + (long)R0 * IMG_W;
    const float* yr = y + base + (long)R0 * IMG_W;

    float rg[7][5];
    #pragma unroll
    for (int j = 0; j < 7; j++) {
        #pragma unroll
        for (int s = 0; s < 5; s++) rg[j][s] = 0.f;
    }
    float S0 = 0.f, S1 = 0.f, S2 = 0.f, S3 = 0.f, S4 = 0.f;
    float local = 0.f;

    // prefetch row 0
    float px = xr[gc], py = yr[gc];
    float pxe = 0.f, pye = 0.f;
    if (extra) { pxe = xr[256 + tid]; pye = yr[256 + tid]; }

    for (int rb = 0; rb < total; rb += 7) {
        #pragma unroll
        for (int j = 0; j < 7; j++) {
            const int r = rb + j;
            if (r < total) {
                const int buf = r & 1;
                sx[buf][tid] = px; sy[buf][tid] = py;
                if (extra) { sx[buf][256 + tid] = pxe; sy[buf][256 + tid] = pye; }
                if (r + 1 < total) {
                    const float* xn = xr + (long)(r + 1) * IMG_W;
                    const float* yn = yr + (long)(r + 1) * IMG_W;
                    px = xn[gc]; py = yn[gc];
                    if (extra) { pxe = xn[256 + tid]; pye = yn[256 + tid]; }
                }
                __syncthreads();

                float ax = 0.f, ay = 0.f, axx = 0.f, ayy = 0.f, axy = 0.f;
                #pragma unroll
                for (int k = 0; k < 7; k++) {
                    float xv = sx[buf][tid + k], yv = sy[buf][tid + k];
                    ax += xv; ay += yv;
                    axx += xv * xv; ayy += yv * yv; axy += xv * yv;
                }
                S0 += ax  - rg[j][0]; rg[j][0] = ax;
                S1 += ay  - rg[j][1]; rg[j][1] = ay;
                S2 += axx - rg[j][2]; rg[j][2] = axx;
                S3 += ayy - rg[j][3]; rg[j][3] = ayy;
                S4 += axy - rg[j][4]; rg[j][4] = axy;

                if (r >= 6 && colok) {
                    const float inv = 1.f / 49.f, COVN = 49.f / 48.f;
                    float ux = S0 * inv, uy = S1 * inv;
                    float uxx = S2 * inv, uyy = S3 * inv, uxy = S4 * inv;
                    float vx  = COVN * (uxx - ux * ux);
                    float vy  = COVN * (uyy - uy * uy);
                    float vxy = COVN * (uxy - ux * uy);
                    float A  = (2.f * ux * uy + 1e-4f) * (2.f * vxy + 9e-4f);
                    float Bd = (ux * ux + uy * uy + 1e-4f) * (vx + vy + 9e-4f);
                    local += A / Bd;
                }
            }
        }
    }

    float tot = blockReduceSum(local, red);
    if (tid == 0) atomicAdd(&g_acc[which], (double)tot);
}

// ---------------------------------------------------------------------------
// Fused elementwise pass, float4-vectorized: L1/MSE reductions + histogram.
// grid.x = B * 64; each block handles 4096 pixels (4 iters x 256 thr x 4 pix).
__global__ __launch_bounds__(256) void elem_kernel(
    const float4* __restrict__ img,   const float4* __restrict__ target,
    const float4* __restrict__ comp0, const float4* __restrict__ comp1,
    const float4* __restrict__ comp2, const float4* __restrict__ real0,
    const float4* __restrict__ real1)
{
    __shared__ unsigned int shist[768];
    __shared__ float red[32];

    const int tid = threadIdx.x;
    for (int i = tid; i < 768; i += 256) shist[i] = 0u;
    __syncthreads();

    const int b = blockIdx.x >> 6;
    const int chunk = blockIdx.x & 63;
    const int HW4 = IMG_HW / 4;               // 65536 float4s per plane
    const long bHW4 = (long)b * HW4;
    const long b3HW4 = (long)b * 3 * HW4;

    float s_cr = 0.f, s_ic = 0.f, s_tr = 0.f, s_light = 0.f, s_mse = 0.f;

    #pragma unroll
    for (int it = 0; it < 4; it++) {
        const int p = chunk * 1024 + it * 256 + tid;
        float4 c1v = comp1[bHW4 + p];
        float4 r1v = real1[bHW4 + p];
        float4 c2v = comp2[bHW4 + p];
        {
            float d;
            d = c2v.x - r1v.x; s_light += d * d;
            d = c2v.y - r1v.y; s_light += d * d;
            d = c2v.z - r1v.z; s_light += d * d;
            d = c2v.w - r1v.w; s_light += d * d;
        }
        #pragma unroll
        for (int c = 0; c < 3; c++) {
            const long idx = b3HW4 + (long)c * HW4 + p;
            float4 iv  = img[idx];
            float4 tv  = target[idx];
            float4 c0v = comp0[idx];
            float4 r0v = real0[idx];
            #define DO_COMP(ix, tx, c0x, r0x, c1x, r1x)                        \
            {                                                                  \
                s_cr += fabsf((c0x) - (r0x));                                  \
                s_ic += fabsf((ix) - (c0x) * (c1x));                           \
                s_tr += fabsf((tx) - (r0x) * (r1x));                           \
                float d_ = (ix) - (tx); s_mse += d_ * d_;                      \
                int bin_ = (int)rintf((tx) * 255.f);                           \
                bin_ = min(max(bin_, 0), 255);                                 \
                atomicAdd(&shist[c * 256 + bin_], 1u);                         \
            }
            DO_COMP(iv.x, tv.x, c0v.x, r0v.x, c1v.x, r1v.x)
            DO_COMP(iv.y, tv.y, c0v.y, r0v.y, c1v.y, r1v.y)
            DO_COMP(iv.z, tv.z, c0v.z, r0v.z, c1v.z, r1v.z)
            DO_COMP(iv.w, tv.w, c0v.w, r0v.w, c1v.w, r1v.w)
            #undef DO_COMP
        }
    }

    float t;
    t = blockReduceSum(s_cr, red);    if (tid == 0) atomicAdd(&g_acc[2], (double)t);
    t = blockReduceSum(s_ic, red);    if (tid == 0) atomicAdd(&g_acc[3], (double)t);
    t = blockReduceSum(s_tr, red);    if (tid == 0) atomicAdd(&g_acc[4], (double)t);
    t = blockReduceSum(s_light, red); if (tid == 0) atomicAdd(&g_acc[5], (double)t);
    t = blockReduceSum(s_mse, red);   if (tid == 0) atomicAdd(&g_acc[6], (double)t);

    __syncthreads();
    for (int i = tid; i < 768; i += 256)
        atomicAdd(&g_hist[b * 768 + i], shist[i]);
}

// ---------------------------------------------------------------------------
__global__ __launch_bounds__(256) void color_gan_kernel(
    const float* __restrict__ color_hist, const float* __restrict__ score)
{
    __shared__ float red[32];
    const float invHW = 1.f / (float)IMG_HW;

    float cs = 0.f;
    for (int i = threadIdx.x; i < NBC * 256; i += 256)
        cs += fabsf(color_hist[i] - (float)g_hist[i] * invHW);

    float gs = 0.f;
    if (threadIdx.x < 16) {
        float z = -score[threadIdx.x];
        gs = fmaxf(z, 0.f) + log1pf(expf(-fabsf(z)));
    }

    float t;
    t = blockReduceSum(cs, red); if (threadIdx.x == 0) g_acc[7] = (double)t;
    t = blockReduceSum(gs, red); if (threadIdx.x == 0) g_acc[8] = (double)t;
}

// ---------------------------------------------------------------------------
__global__ void finalize_kernel(float* out, int out_size) {
    if (threadIdx.x != 0 || blockIdx.x != 0) return;
    const double nS = 48.0 * 506.0 * 506.0;
    double ssim0 = g_acc[0] / nS;
    double ssim1 = g_acc[1] / nS;
    double r     = (1.0 - ssim0) + g_acc[2] / N3 + g_acc[3] / N3 + g_acc[4] / N3;
    double light = g_acc[5] / NHW;
    double color = g_acc[7] / (48.0 * 256.0);
    double outl  = (1.0 - ssim1) + g_acc[6] / N3;
    double gan   = g_acc[8] / 16.0;
    double loss  = r + light + 0.1 * color + outl + 0.05 * gan;

    float v[7] = {(float)loss, (float)loss, (float)r, (float)light,
                  (float)color, (float)outl, (float)gan};
    const float* src = (out_size == 6) ? (v + 1) : v;
    int n = out_size < 7 ? out_size : 7;
    for (int i = 0; i < n; i++) out[i] = src[i];
}

// ---------------------------------------------------------------------------
extern "C" void kernel_launch(void* const* d_in, const int* in_sizes, int n_in,
                              void* d_out, int out_size) {
    const float* img    = (const float*)d_in[0];
    const float* target = (const float*)d_in[1];
    const float* comp0  = (const float*)d_in[2];
    const float* comp1  = (const float*)d_in[3];
    const float* comp2  = (const float*)d_in[4];
    const float* real0  = (const float*)d_in[5];
    const float* real1  = (const float*)d_in[6];
    const float* chist  = (const float*)d_in[7];
    const float* score  = (const float*)d_in[8];
    float* out = (float*)d_out;

    init_kernel<<<48, 256>>>();

    dim3 sgrid(2, 8, NBC);
    ssim_kernel<<<sgrid, 256>>>(comp0, real0, 0);
    ssim_kernel<<<sgrid, 256>>>(img, target, 1);

    elem_kernel<<<16 * 64, 256>>>(
        (const float4*)img, (const float4*)target, (const float4*)comp0,
        (const float4*)comp1, (const float4*)comp2, (const float4*)real0,
        (const float4*)real1);

    color_gan_kernel<<<1, 256>>>(chist, score);

    finalize_kernel<<<1, 32>>>(out, out_size);
}

// round 3
// speedup vs baseline: 1.7763x; 1.3335x over previous
#include <cuda_runtime.h>
#include <math.h>

// ---------------------------------------------------------------------------
// LLIE loss: 2x SSIM(7x7, valid) + L1/MSE reductions + 256-bin histogram color
// loss + BCE-with-logits GAN loss.  B=16, C=3, H=W=512. SSIM valid out 506x506.
// ---------------------------------------------------------------------------

#define IMG_W   512
#define IMG_HW  (512 * 512)
#define OUT_W   506
#define NBC     48
#define N3      12582912.0
#define NHW     4194304.0

// 0 ssim0, 1 ssim1, 2 l1(all three), 5 mse light, 6 mse out, 7 color, 8 gan
__device__ double g_acc[9];
__device__ unsigned int g_hist[NBC * 256];

// ---------------- f32x2 packed helpers (sm_103a) ---------------------------
typedef unsigned long long u64t;
__device__ __forceinline__ u64t f2_pack(float x, float y) {
    u64t r; asm("mov.b64 %0,{%1,%2};" : "=l"(r) : "f"(x), "f"(y)); return r;
}
__device__ __forceinline__ void f2_unpack(u64t p, float& x, float& y) {
    asm("mov.b64 {%0,%1},%2;" : "=f"(x), "=f"(y) : "l"(p));
}
__device__ __forceinline__ u64t f2_add(u64t a, u64t b) {
    u64t d; asm("add.rn.f32x2 %0,%1,%2;" : "=l"(d) : "l"(a), "l"(b)); return d;
}
__device__ __forceinline__ u64t f2_fma(u64t a, u64t b, u64t c) {
    u64t d; asm("fma.rn.f32x2 %0,%1,%2,%3;" : "=l"(d) : "l"(a), "l"(b), "l"(c)); return d;
}

// ---------------------------------------------------------------------------
__device__ __forceinline__ float blockReduceSum(float v, float* red) {
    #pragma unroll
    for (int o = 16; o > 0; o >>= 1) v += __shfl_down_sync(0xffffffffu, v, o);
    int lane = threadIdx.x & 31, wid = threadIdx.x >> 5;
    if (lane == 0) red[wid] = v;
    __syncthreads();
    v = (threadIdx.x < (blockDim.x >> 5)) ? red[threadIdx.x] : 0.f;
    if (wid == 0) {
        #pragma unroll
        for (int o = 16; o > 0; o >>= 1) v += __shfl_down_sync(0xffffffffu, v, o);
    }
    __syncthreads();
    return v;
}

// ---------------------------------------------------------------------------
__global__ void init_kernel() {
    int i = blockIdx.x * blockDim.x + threadIdx.x;
    if (i < 9) g_acc[i] = 0.0;
    for (int j = i; j < NBC * 256; j += gridDim.x * blockDim.x) g_hist[j] = 0u;
}

// ---------------------------------------------------------------------------
// Sliding-window SSIM, 7-row grouped.
// Thread owns one column; vertical 7-row window kept as running sums with a
// 7-deep static register ring. Rows come through a float2-packed smem buffer
// of 7 rows; 2 barriers per 7 rows. Next group's globals prefetched into regs.
// Grid: (2 col-blocks, 4 row strips of 127, 48 planes), 288 threads
// (256 compute cols + 6 halo-loader lanes in warp 8).
__global__ __launch_bounds__(288) void ssim_kernel(
    const float* __restrict__ x, const float* __restrict__ y, int which)
{
    __shared__ float2 s[7][264];
    __shared__ float red[32];

    const int tid = threadIdx.x;
    const int c0 = blockIdx.x << 8;            // 0 or 256
    const int R0 = blockIdx.y * 127;           // output-row strip start
    const int rows = min(127, OUT_W - R0);     // 127 or 125
    const int total = rows + 6;                // input rows this strip
    const long base = (long)blockIdx.z * IMG_HW;
    const int gc = c0 + tid;                   // global column for loads
    const bool loadok = (c0 == 0) ? (tid < 262) : (tid < 256);
    const bool compok = (tid < 256) && (gc < OUT_W);

    const float* xr = x + base + (long)R0 * IMG_W;
    const float* yr = y + base + (long)R0 * IMG_W;

    // 7-deep register ring of horizontal window sums (packed)
    u64t rgA[7], rgQ[7];
    float rgXY[7];
    #pragma unroll
    for (int j = 0; j < 7; j++) { rgA[j] = 0ull; rgQ[j] = 0ull; rgXY[j] = 0.f; }
    u64t SA = 0ull, SQ = 0ull;
    float SXY = 0.f;
    float local = 0.f;
    const u64t NEG1 = f2_pack(-1.f, -1.f);

    // prefetch group 0
    float px[7], py[7];
    #pragma unroll
    for (int j = 0; j < 7; j++) {
        px[j] = 0.f; py[j] = 0.f;
        if (loadok) {  // j < total always for first group (total >= 131)
            px[j] = xr[(long)j * IMG_W + gc];
            py[j] = yr[(long)j * IMG_W + gc];
        }
    }

    const int ngroups = (total + 6) / 7;       // 19
    for (int g = 0; g < ngroups; g++) {
        const int gr = g * 7;

        // store current group
        if (loadok) {
            #pragma unroll
            for (int j = 0; j < 7; j++)
                if (gr + j < total) s[j][tid] = make_float2(px[j], py[j]);
        }
        __syncthreads();

        // prefetch next group
        {
            const int nb = gr + 7;
            if (loadok && nb < total) {
                #pragma unroll
                for (int j = 0; j < 7; j++) {
                    const int rr = nb + j;
                    if (rr < total) {
                        px[j] = xr[(long)rr * IMG_W + gc];
                        py[j] = yr[(long)rr * IMG_W + gc];
                    }
                }
            }
        }

        // process 7 rows
        if (compok) {
            #pragma unroll
            for (int j = 0; j < 7; j++) {
                const int rr = gr + j;
                if (rr < total) {
                    // horizontal 7-tap of packed (x,y): sums, squares, xy
                    u64t a01 = 0ull, q01 = 0ull;
                    float sxy = 0.f;
                    #pragma unroll
                    for (int k = 0; k < 7; k++) {
                        float2 v = s[j][tid + k];
                        u64t vv = f2_pack(v.x, v.y);
                        a01 = f2_add(a01, vv);
                        q01 = f2_fma(vv, vv, q01);
                        sxy = fmaf(v.x, v.y, sxy);
                    }
                    // vertical running-sum update (ring slot j == rr % 7)
                    SA = f2_add(SA, a01); SA = f2_fma(rgA[j], NEG1, SA); rgA[j] = a01;
                    SQ = f2_add(SQ, q01); SQ = f2_fma(rgQ[j], NEG1, SQ); rgQ[j] = q01;
                    SXY += sxy - rgXY[j]; rgXY[j] = sxy;

                    if (rr >= 6) {
                        const float inv = 1.f / 49.f, COVN = 49.f / 48.f;
                        float S0, S1, S2, S3;
                        f2_unpack(SA, S0, S1);
                        f2_unpack(SQ, S2, S3);
                        float ux = S0 * inv, uy = S1 * inv;
                        float uxx = S2 * inv, uyy = S3 * inv, uxy = SXY * inv;
                        float vx  = COVN * fmaf(-ux, ux, uxx);
                        float vy  = COVN * fmaf(-uy, uy, uyy);
                        float vxy = COVN * fmaf(-ux, uy, uxy);
                        float ux2 = ux + ux;
                        float num = fmaf(ux2, uy, 1e-4f) * fmaf(2.f, vxy, 9e-4f);
                        float den = fmaf(ux, ux, fmaf(uy, uy, 1e-4f)) *
                                    (vx + vy + 9e-4f);
                        local += __fdividef(num, den);
                    }
                }
            }
        }
        __syncthreads();   // protect smem reuse next group
    }

    float tot = blockReduceSum(local, red);
    if (tid == 0) atomicAdd(&g_acc[which], (double)tot);
}

// ---------------------------------------------------------------------------
// Fused elementwise pass, float4: merged-L1 + MSEs + target histogram.
// grid.x = B * 64; each block handles 4096 pixels.
__global__ __launch_bounds__(256, 4) void elem_kernel(
    const float4* __restrict__ img,   const float4* __restrict__ target,
    const float4* __restrict__ comp0, const float4* __restrict__ comp1,
    const float4* __restrict__ comp2, const float4* __restrict__ real0,
    const float4* __restrict__ real1)
{
    __shared__ unsigned int shist[768];
    __shared__ float red[32];

    const int tid = threadIdx.x;
    for (int i = tid; i < 768; i += 256) shist[i] = 0u;
    __syncthreads();

    const int b = blockIdx.x >> 6;
    const int chunk = blockIdx.x & 63;
    const int HW4 = IMG_HW / 4;
    const long bHW4 = (long)b * HW4;
    const long b3HW4 = (long)b * 3 * HW4;

    float s_l1 = 0.f, s_light = 0.f, s_mse = 0.f;

    #pragma unroll
    for (int it = 0; it < 4; it++) {
        const int p = chunk * 1024 + it * 256 + tid;
        float4 r1v = real1[bHW4 + p];
        {
            float4 c2v = comp2[bHW4 + p];
            float d;
            d = c2v.x - r1v.x; s_light = fmaf(d, d, s_light);
            d = c2v.y - r1v.y; s_light = fmaf(d, d, s_light);
            d = c2v.z - r1v.z; s_light = fmaf(d, d, s_light);
            d = c2v.w - r1v.w; s_light = fmaf(d, d, s_light);
        }
        float4 c1v = comp1[bHW4 + p];
        #pragma unroll
        for (int c = 0; c < 3; c++) {
            const long idx = b3HW4 + (long)c * HW4 + p;
            float4 iv  = img[idx];
            float4 tv  = target[idx];
            float4 c0v = comp0[idx];
            float4 r0v = real0[idx];
            #define DO_COMP(ix, tx, c0x, r0x, c1x, r1x)                        \
            {                                                                  \
                s_l1 += fabsf((c0x) - (r0x))                                   \
                      + fabsf((ix) - (c0x) * (c1x))                            \
                      + fabsf((tx) - (r0x) * (r1x));                           \
                float d_ = (ix) - (tx); s_mse = fmaf(d_, d_, s_mse);           \
                int bin_ = (int)rintf((tx) * 255.f);                           \
                bin_ = min(max(bin_, 0), 255);                                 \
                atomicAdd(&shist[c * 256 + bin_], 1u);                         \
            }
            DO_COMP(iv.x, tv.x, c0v.x, r0v.x, c1v.x, r1v.x)
            DO_COMP(iv.y, tv.y, c0v.y, r0v.y, c1v.y, r1v.y)
            DO_COMP(iv.z, tv.z, c0v.z, r0v.z, c1v.z, r1v.z)
            DO_COMP(iv.w, tv.w, c0v.w, r0v.w, c1v.w, r1v.w)
            #undef DO_COMP
        }
    }

    float t;
    t = blockReduceSum(s_l1, red);    if (tid == 0) atomicAdd(&g_acc[2], (double)t);
    t = blockReduceSum(s_light, red); if (tid == 0) atomicAdd(&g_acc[5], (double)t);
    t = blockReduceSum(s_mse, red);   if (tid == 0) atomicAdd(&g_acc[6], (double)t);

    __syncthreads();
    for (int i = tid; i < 768; i += 256)
        atomicAdd(&g_hist[b * 768 + i], shist[i]);
}

// ---------------------------------------------------------------------------
__global__ __launch_bounds__(256) void color_gan_kernel(
    const float* __restrict__ color_hist, const float* __restrict__ score)
{
    __shared__ float red[32];
    const float invHW = 1.f / (float)IMG_HW;

    float cs = 0.f;
    for (int i = threadIdx.x; i < NBC * 256; i += 256)
        cs += fabsf(color_hist[i] - (float)g_hist[i] * invHW);

    float gs = 0.f;
    if (threadIdx.x < 16) {
        float z = -score[threadIdx.x];
        gs = fmaxf(z, 0.f) + log1pf(expf(-fabsf(z)));
    }

    float t;
    t = blockReduceSum(cs, red); if (threadIdx.x == 0) g_acc[7] = (double)t;
    t = blockReduceSum(gs, red); if (threadIdx.x == 0) g_acc[8] = (double)t;
}

// ---------------------------------------------------------------------------
__global__ void finalize_kernel(float* out, int out_size) {
    if (threadIdx.x != 0 || blockIdx.x != 0) return;
    const double nS = 48.0 * 506.0 * 506.0;
    double ssim0 = g_acc[0] / nS;
    double ssim1 = g_acc[1] / nS;
    double r     = (1.0 - ssim0) + g_acc[2] / N3;
    double light = g_acc[5] / NHW;
    double color = g_acc[7] / (48.0 * 256.0);
    double outl  = (1.0 - ssim1) + g_acc[6] / N3;
    double gan   = g_acc[8] / 16.0;
    double loss  = r + light + 0.1 * color + outl + 0.05 * gan;

    float v[7] = {(float)loss, (float)loss, (float)r, (float)light,
                  (float)color, (float)outl, (float)gan};
    const float* src = (out_size == 6) ? (v + 1) : v;
    int n = out_size < 7 ? out_size : 7;
    for (int i = 0; i < n; i++) out[i] = src[i];
}

// ---------------------------------------------------------------------------
extern "C" void kernel_launch(void* const* d_in, const int* in_sizes, int n_in,
                              void* d_out, int out_size) {
    const float* img    = (const float*)d_in[0];
    const float* target = (const float*)d_in[1];
    const float* comp0  = (const float*)d_in[2];
    const float* comp1  = (const float*)d_in[3];
    const float* comp2  = (const float*)d_in[4];
    const float* real0  = (const float*)d_in[5];
    const float* real1  = (const float*)d_in[6];
    const float* chist  = (const float*)d_in[7];
    const float* score  = (const float*)d_in[8];
    float* out = (float*)d_out;

    init_kernel<<<48, 256>>>();

    dim3 sgrid(2, 4, NBC);
    ssim_kernel<<<sgrid, 288>>>(comp0, real0, 0);
    ssim_kernel<<<sgrid, 288>>>(img, target, 1);

    elem_kernel<<<16 * 64, 256>>>(
        (const float4*)img, (const float4*)target, (const float4*)comp0,
        (const float4*)comp1, (const float4*)comp2, (const float4*)real0,
        (const float4*)real1);

    color_gan_kernel<<<1, 256>>>(chist, score);

    finalize_kernel<<<1, 32>>>(out, out_size);
}